// round 13
// baseline (speedup 1.0000x reference)
#include <cuda_runtime.h>
#include <cuda_bf16.h>
#include <cstdint>

// ---------------- dims ----------------
#define T_LEN  1024
#define NBG    16       // batch groups (16 batch each)
#define NGG    8        // gate-slice CTAs per group
#define BB     16
#define NTHR   512      // 2 groups x 256 threads

// ---------------- smem layout (bytes) ----------------
// W frag regions: [hi_t01, hi_t23, lo_t01, lo_t23], each [gate4][ks20][lane32][16B]
#define WREG    40960
#define W_OFF   0                        // 163840 total
#define HX_OFF  163840                   // per group: {hi 10240 | lo 10240}
#define HXG     20480
#define SP_OFF  204800                   // per group: [b16][132 floats] = 8448
#define SPG     8448
#define SMEM_TOTAL (SP_OFF + 2 * SPG)    // 221696

// ---------------- static scratch ----------------
// hx ring in fragment layout: [t][bg]{hi 10240 | lo 10240}; x pre-staged at ks16..19
__device__ char          g_B[(size_t)(T_LEN + 1) * NBG * 20480];
__device__ float         g_Hf[256][256];
__device__ unsigned int  g_cnt[NBG * 32];

// ---------------- helpers ----------------
__device__ __forceinline__ unsigned int ld_acq(const unsigned int* p) {
  unsigned int v;
  asm volatile("ld.acquire.gpu.global.u32 %0, [%1];" : "=r"(v) : "l"(p) : "memory");
  return v;
}
__device__ __forceinline__ void red_rel(unsigned int* p) {
  asm volatile("red.release.gpu.global.add.u32 [%0], 1;" :: "l"(p) : "memory");
}
__device__ __forceinline__ void bar_grp(int id) {
  asm volatile("bar.sync %0, 256;" :: "r"(id) : "memory");
}
__device__ __forceinline__ float fsig(float x) {
  x = fminf(fmaxf(x, -15.0f), 15.0f);
  return __fdividef(1.0f, 1.0f + __expf(-x));
}
__device__ __forceinline__ float ftanh(float x) {
  x = fminf(fmaxf(x, -15.0f), 15.0f);
  float e = __expf(-2.0f * x);
  return __fdividef(1.0f - e, 1.0f + e);
}
__device__ __forceinline__ void mma16816(float* d, const uint4& a,
                                         uint32_t b0, uint32_t b1) {
  asm volatile(
      "mma.sync.aligned.m16n8k16.row.col.f32.bf16.bf16.f32 "
      "{%0,%1,%2,%3}, {%4,%5,%6,%7}, {%8,%9}, {%0,%1,%2,%3};"
      : "+f"(d[0]), "+f"(d[1]), "+f"(d[2]), "+f"(d[3])
      : "r"(a.x), "r"(a.y), "r"(a.z), "r"(a.w), "r"(b0), "r"(b1));
}
// A-frag offset (batch b, k_in) within one kstep's 512B frag
__device__ __forceinline__ int hx_frag_off(int b, int k_in) {
  int u    = (k_in & 7) >> 1;
  int half = k_in & 1;
  int reg  = ((b >> 3) & 1) + ((k_in >> 3) & 1) * 2;
  return ((b & 7) * 4 + u) * 16 + reg * 4 + half * 2;
}

// ---------------- prep kernels ----------------
__global__ void reset_kernel() {
  if (threadIdx.x < NBG * 32) g_cnt[threadIdx.x] = 0u;
}
// stage x (hi/lo) into ring k-steps 16..19 for all t
__global__ void xprep_kernel(const float* __restrict__ x) {
  int id  = blockIdx.x * 256 + threadIdx.x;      // 16,777,216
  int i   = id & 63;
  int t   = (id >> 6) & 1023;
  int bgl = id >> 16;
  float v = x[(size_t)bgl * (T_LEN * 64) + t * 64 + i];
  __nv_bfloat16 hi = __float2bfloat16(v);
  __nv_bfloat16 lo = __float2bfloat16(v - __bfloat162float(hi));
  int bg = bgl >> 4, b = bgl & 15;
  int ks = 16 + (i >> 4);
  int off = ks * 512 + hx_frag_off(b, i & 15);
  char* base = g_B + ((size_t)t * NBG + bg) * 20480;
  *(__nv_bfloat16*)(base + off)         = hi;
  *(__nv_bfloat16*)(base + 10240 + off) = lo;
}

// ---------------- main persistent kernel: 2 independent pipelines ----------------
__global__ void __launch_bounds__(NTHR, 1) lstm_kernel(
    const float* __restrict__ W_ih, const float* __restrict__ W_hh,
    const float* __restrict__ b_ih, const float* __restrict__ b_hh) {
  extern __shared__ char smem[];
  const int tid  = threadIdx.x;
  const int wid  = tid >> 5;
  const int lane = tid & 31;
  const int grp  = wid >> 3;          // pipeline 0 / 1
  const int gwid = wid & 7;           // warp within pipeline
  const int gtid = tid & 255;         // thread within pipeline
  const int cg   = blockIdx.x >> 3;   // 0..7
  const int gg   = blockIdx.x & 7;    // gate slice
  const int c0   = gg * 32;
  const int bg   = cg + grp * 8;      // this pipeline's batch group
  const int barid = 1 + grp;

  // ---- one-time: W slice -> smem frags (all 512 threads) ----
  for (int idx = tid; idx < 128 * 320; idx += NTHR) {
    int r = idx / 320, k = idx - r * 320;
    int gate = r >> 5;
    int gr = gate * 256 + c0 + (r & 31);
    float v = (k < 256) ? W_hh[gr * 256 + k] : W_ih[gr * 64 + (k - 256)];
    __nv_bfloat16 hi = __float2bfloat16(v);
    __nv_bfloat16 lo = __float2bfloat16(v - __bfloat162float(hi));
    int ks = k >> 4, ki = k & 15;
    int u = (ki & 7) >> 1, half = ki & 1, rh = (ki >> 3) & 1;
    int j = (r >> 3) & 3;
    int off = gate * 10240 + ks * 512 + ((r & 7) * 4 + u) * 16 +
              (j & 1) * 8 + rh * 4 + half * 2;
    int regidx = j >> 1;
    *(__nv_bfloat16*)(smem + W_OFF + regidx * WREG + off)       = hi;
    *(__nv_bfloat16*)(smem + W_OFF + (2 + regidx) * WREG + off) = lo;
  }

  char* hsm = smem + HX_OFF + grp * HXG;
  float* sp = (float*)(smem + SP_OFF + grp * SPG);

  // zero h region of both planes (ks 0..15): 1024 x 16B chunks per group
  for (int i = gtid; i < 1024; i += 256) {
    int off = (i >> 9) * 10240 + (i & 511) * 16;
    *(uint4*)(hsm + off) = make_uint4(0, 0, 0, 0);
  }

  // h copy-in chunk offsets: 4 x 16B per thread (16KB h region, both planes)
  int hoff[4];
#pragma unroll
  for (int i = 0; i < 4; i++) {
    int q = gtid + i * 256;
    hoff[i] = (q >> 9) * 10240 + (q & 511) * 16;
  }
  // x stage: one 16B chunk per thread (4KB x region, both planes)
  const int xoff = (gtid >> 7) * 10240 + 8192 + (gtid & 127) * 16;
  // preload x(0)
  {
    const char* src = g_B + (size_t)bg * 20480;
    *(uint4*)(hsm + xoff) = __ldcg((const uint4*)(src + xoff));
  }

  // MMA mapping: ns = gate slice warp, kh = interleaved k-half
  const int ns = gwid & 3;
  const int kh = gwid >> 2;
  const char* pAh = hsm + kh * 512 + lane * 16;     // + j*1024
  const char* pAl = pAh + 10240;
  const char* pB  = smem + W_OFF + ns * 10240 + kh * 512 + lane * 16;

  // spill mapping
  const int sq  = lane >> 2;
  const int cp2 = (lane & 3) * 2;

  // epilogue mapping: (eb, ehc) and (eb+8, ehc)
  const int eb  = gtid >> 5;
  const int ehc = gtid & 31;
  const int eks = gg * 2 + (ehc >> 4);
  const int ekin = ehc & 15;
  float bias[4];
#pragma unroll
  for (int g = 0; g < 4; g++)
    bias[g] = b_ih[g * 256 + c0 + ehc] + b_hh[g * 256 + c0 + ehc];
  float cs[2] = {0.f, 0.f};

  unsigned int* flag = &g_cnt[bg * 32];
  __syncthreads();   // W + hsm init complete

  for (int t = 0; t < T_LEN; t++) {
    const char* ringT  = g_B + ((size_t)t * NBG + bg) * 20480;
    char*       ringT1 = g_B + ((size_t)(t + 1) * NBG + bg) * 20480;

    // ---- prefetch x(t+1) (pre-staged, h-independent) ----
    uint4 xv = __ldcg((const uint4*)(ringT1 + xoff));

    // ---- wait for h(t); issue h LDGs immediately after ----
    uint4 hv0, hv1, hv2, hv3;
    if (t) {
      unsigned int target = (unsigned int)(NGG * t);
      while (ld_acq(flag) < target) { }
      hv0 = __ldcg((const uint4*)(ringT + hoff[0]));
      hv1 = __ldcg((const uint4*)(ringT + hoff[1]));
      hv2 = __ldcg((const uint4*)(ringT + hoff[2]));
      hv3 = __ldcg((const uint4*)(ringT + hoff[3]));
    }

    float acc[16];
#pragma unroll
    for (int i = 0; i < 16; i++) acc[i] = 0.f;

    // ---- x-part MMAs (j = 8,9 -> ksteps 16..19) while h LDGs fly ----
#pragma unroll
    for (int j = 8; j < 10; j++) {
      uint4 aH  = *(const uint4*)(pAh + j * 1024);
      uint4 aL  = *(const uint4*)(pAl + j * 1024);
      uint4 bh0 = *(const uint4*)(pB + j * 1024);
      uint4 bh1 = *(const uint4*)(pB + WREG + j * 1024);
      uint4 bl0 = *(const uint4*)(pB + 2 * WREG + j * 1024);
      uint4 bl1 = *(const uint4*)(pB + 3 * WREG + j * 1024);
      mma16816(acc + 0,  aH, bh0.x, bh0.y);
      mma16816(acc + 0,  aH, bl0.x, bl0.y);
      mma16816(acc + 0,  aL, bh0.x, bh0.y);
      mma16816(acc + 4,  aH, bh0.z, bh0.w);
      mma16816(acc + 4,  aH, bl0.z, bl0.w);
      mma16816(acc + 4,  aL, bh0.z, bh0.w);
      mma16816(acc + 8,  aH, bh1.x, bh1.y);
      mma16816(acc + 8,  aH, bl1.x, bl1.y);
      mma16816(acc + 8,  aL, bh1.x, bh1.y);
      mma16816(acc + 12, aH, bh1.z, bh1.w);
      mma16816(acc + 12, aH, bl1.z, bl1.w);
      mma16816(acc + 12, aL, bh1.z, bh1.w);
    }

    // ---- land h frags, group barrier ----
    if (t) {
      *(uint4*)(hsm + hoff[0]) = hv0;
      *(uint4*)(hsm + hoff[1]) = hv1;
      *(uint4*)(hsm + hoff[2]) = hv2;
      *(uint4*)(hsm + hoff[3]) = hv3;
    }
    bar_grp(barid);

    // ---- h-part MMAs (j = 0..7 -> ksteps 0..15) ----
#pragma unroll
    for (int j = 0; j < 8; j++) {
      uint4 aH  = *(const uint4*)(pAh + j * 1024);
      uint4 aL  = *(const uint4*)(pAl + j * 1024);
      uint4 bh0 = *(const uint4*)(pB + j * 1024);
      uint4 bh1 = *(const uint4*)(pB + WREG + j * 1024);
      uint4 bl0 = *(const uint4*)(pB + 2 * WREG + j * 1024);
      uint4 bl1 = *(const uint4*)(pB + 3 * WREG + j * 1024);
      mma16816(acc + 0,  aH, bh0.x, bh0.y);
      mma16816(acc + 0,  aH, bl0.x, bl0.y);
      mma16816(acc + 0,  aL, bh0.x, bh0.y);
      mma16816(acc + 4,  aH, bh0.z, bh0.w);
      mma16816(acc + 4,  aH, bl0.z, bl0.w);
      mma16816(acc + 4,  aL, bh0.z, bh0.w);
      mma16816(acc + 8,  aH, bh1.x, bh1.y);
      mma16816(acc + 8,  aH, bl1.x, bl1.y);
      mma16816(acc + 8,  aL, bh1.x, bh1.y);
      mma16816(acc + 12, aH, bh1.z, bh1.w);
      mma16816(acc + 12, aH, bl1.z, bl1.w);
      mma16816(acc + 12, aL, bh1.z, bh1.w);
    }

    // ---- spill-combine into single buffer: kh1 stores, kh0 adds ----
    if (kh == 1) {
#pragma unroll
      for (int tl = 0; tl < 4; tl++) {
        int r = ns * 32 + tl * 8 + cp2;
        *(float2*)(sp + sq * 132 + r)       = make_float2(acc[tl * 4], acc[tl * 4 + 1]);
        *(float2*)(sp + (sq + 8) * 132 + r) = make_float2(acc[tl * 4 + 2], acc[tl * 4 + 3]);
      }
    }
    bar_grp(barid);
    if (kh == 0) {
#pragma unroll
      for (int tl = 0; tl < 4; tl++) {
        int r = ns * 32 + tl * 8 + cp2;
        float2 p0 = *(const float2*)(sp + sq * 132 + r);
        float2 p1 = *(const float2*)(sp + (sq + 8) * 132 + r);
        *(float2*)(sp + sq * 132 + r) =
            make_float2(acc[tl * 4] + p0.x, acc[tl * 4 + 1] + p0.y);
        *(float2*)(sp + (sq + 8) * 132 + r) =
            make_float2(acc[tl * 4 + 2] + p1.x, acc[tl * 4 + 3] + p1.y);
      }
    }
    bar_grp(barid);

    // ---- epilogue: activations, c/h, publish h(t+1), stage x(t+1) ----
#pragma unroll
    for (int uu = 0; uu < 2; uu++) {
      int b = eb + uu * 8;
      float gi = sp[b * 132 +  0 + ehc] + bias[0];
      float gf = sp[b * 132 + 32 + ehc] + bias[1];
      float gc = sp[b * 132 + 64 + ehc] + bias[2];
      float go = sp[b * 132 + 96 + ehc] + bias[3];
      float iv = fsig(gi), fv = fsig(gf), cv = ftanh(gc), ov = fsig(go);
      float cn = fv * cs[uu] + iv * cv;
      cs[uu] = cn;
      float hvv = ov * ftanh(cn);
      __nv_bfloat16 hi = __float2bfloat16(hvv);
      __nv_bfloat16 lo = __float2bfloat16(hvv - __bfloat162float(hi));
      int off = eks * 512 + hx_frag_off(b, ekin);
      *(__nv_bfloat16*)(ringT1 + off)         = hi;
      *(__nv_bfloat16*)(ringT1 + 10240 + off) = lo;
      if (t == T_LEN - 1) g_Hf[bg * BB + b][c0 + ehc] = hvv;
    }
    *(uint4*)(hsm + xoff) = xv;     // stage x(t+1) (x(t) fully consumed)
    bar_grp(barid);
    if (gtid == 0) red_rel(flag);
  }
}

// ---------------- fc ----------------
__global__ void fc_kernel(const float* __restrict__ fc_w,
                          const float* __restrict__ fc_b,
                          float* __restrict__ out) {
  int b = blockIdx.x;
  float s = g_Hf[b][threadIdx.x] * fc_w[threadIdx.x];
#pragma unroll
  for (int o = 16; o; o >>= 1) s += __shfl_xor_sync(0xFFFFFFFFu, s, o);
  __shared__ float ps[8];
  if ((threadIdx.x & 31) == 0) ps[threadIdx.x >> 5] = s;
  __syncthreads();
  if (threadIdx.x == 0) {
    float tt = 0.f;
#pragma unroll
    for (int i = 0; i < 8; i++) tt += ps[i];
    out[b] = tt + fc_b[0];
  }
}

// ---------------- launch ----------------
extern "C" void kernel_launch(void* const* d_in, const int* in_sizes, int n_in,
                              void* d_out, int out_size) {
  const float* x    = (const float*)d_in[0];
  const float* W_ih = (const float*)d_in[1];
  const float* W_hh = (const float*)d_in[2];
  const float* b_ih = (const float*)d_in[3];
  const float* b_hh = (const float*)d_in[4];
  const float* fc_w = (const float*)d_in[5];
  const float* fc_b = (const float*)d_in[6];
  float* out = (float*)d_out;

  static bool init = false;
  if (!init) {
    cudaFuncSetAttribute(lstm_kernel,
                         cudaFuncAttributeMaxDynamicSharedMemorySize, SMEM_TOTAL);
    init = true;
  }

  reset_kernel<<<1, 512>>>();
  xprep_kernel<<<65536, 256>>>(x);
  lstm_kernel<<<NBG * NGG / 2, NTHR, SMEM_TOTAL>>>(W_ih, W_hh, b_ih, b_hh);
  fc_kernel<<<256, 256>>>(fc_w, fc_b, out);
}

// round 14
// speedup vs baseline: 1.3599x; 1.3599x over previous
#include <cuda_runtime.h>
#include <cuda_bf16.h>
#include <cstdint>

// ---------------- dims ----------------
#define T_LEN  1024
#define NBG    16       // batch groups (16 batch each)
#define NSL    16       // h-col slices per group (16 cols x 4 gates = 64 rows per CTA)
#define BB     16
#define NTHR   256

// ---------------- smem layout (bytes) ----------------
#define W_OFF   0
#define WPL     40960                  // per-plane W frags: [rw4][ks20][512B]
#define HX_OFF  81920                  // hx: {hi 10240 | lo 10240}
#define SP_OFF  102400                 // spill: [kh2][b16][70 floats]
#define SPSTR   70
#define SMEM_TOTAL (SP_OFF + 2 * 16 * SPSTR * 4)   // 111360 -> 2 CTAs/SM

// ---------------- static scratch ----------------
// hx ring in fragment layout: [t][bg]{hi 10240 | lo 10240}; x pre-staged at ks16..19
__device__ char          g_B[(size_t)(T_LEN + 1) * NBG * 20480];
__device__ float         g_Hf[256][256];
__device__ unsigned int  g_cnt[NBG * 32];

// ---------------- helpers ----------------
__device__ __forceinline__ unsigned int ld_acq(const unsigned int* p) {
  unsigned int v;
  asm volatile("ld.acquire.gpu.global.u32 %0, [%1];" : "=r"(v) : "l"(p) : "memory");
  return v;
}
__device__ __forceinline__ void red_rel(unsigned int* p) {
  asm volatile("red.release.gpu.global.add.u32 [%0], 1;" :: "l"(p) : "memory");
}
__device__ __forceinline__ float fsig(float x) {
  x = fminf(fmaxf(x, -15.0f), 15.0f);
  return __fdividef(1.0f, 1.0f + __expf(-x));
}
__device__ __forceinline__ float ftanh(float x) {
  x = fminf(fmaxf(x, -15.0f), 15.0f);
  float e = __expf(-2.0f * x);
  return __fdividef(1.0f - e, 1.0f + e);
}
__device__ __forceinline__ void mma16816(float* d, const uint4& a,
                                         uint32_t b0, uint32_t b1) {
  asm volatile(
      "mma.sync.aligned.m16n8k16.row.col.f32.bf16.bf16.f32 "
      "{%0,%1,%2,%3}, {%4,%5,%6,%7}, {%8,%9}, {%0,%1,%2,%3};"
      : "+f"(d[0]), "+f"(d[1]), "+f"(d[2]), "+f"(d[3])
      : "r"(a.x), "r"(a.y), "r"(a.z), "r"(a.w), "r"(b0), "r"(b1));
}
// A-frag offset (batch b, k_in) within one kstep's 512B frag
__device__ __forceinline__ int hx_frag_off(int b, int k_in) {
  int u    = (k_in & 7) >> 1;
  int half = k_in & 1;
  int reg  = ((b >> 3) & 1) + ((k_in >> 3) & 1) * 2;
  return ((b & 7) * 4 + u) * 16 + reg * 4 + half * 2;
}
// B-frag byte offset (row-in-16 r16, k_in) within its 512B block (2 n8 tiles)
__device__ __forceinline__ int b_frag_off(int r16, int k_in) {
  return (((r16 & 7) * 4 + ((k_in & 7) >> 1)) << 4) + ((r16 >> 3) & 1) * 8 +
         ((k_in >> 3) & 1) * 4 + (k_in & 1) * 2;
}

// ---------------- prep kernels ----------------
__global__ void reset_kernel() {
  if (threadIdx.x < NBG * 32) g_cnt[threadIdx.x] = 0u;
}
// stage x (hi/lo) into ring k-steps 16..19 for all t
__global__ void xprep_kernel(const float* __restrict__ x) {
  int id  = blockIdx.x * 256 + threadIdx.x;      // 16,777,216
  int i   = id & 63;
  int t   = (id >> 6) & 1023;
  int bgl = id >> 16;
  float v = x[(size_t)bgl * (T_LEN * 64) + t * 64 + i];
  __nv_bfloat16 hi = __float2bfloat16(v);
  __nv_bfloat16 lo = __float2bfloat16(v - __bfloat162float(hi));
  int bg = bgl >> 4, b = bgl & 15;
  int ks = 16 + (i >> 4);
  int off = ks * 512 + hx_frag_off(b, i & 15);
  char* base = g_B + ((size_t)t * NBG + bg) * 20480;
  *(__nv_bfloat16*)(base + off)         = hi;
  *(__nv_bfloat16*)(base + 10240 + off) = lo;
}

// ---------------- main persistent kernel: 2 CTAs per SM ----------------
__global__ void __launch_bounds__(NTHR, 2) lstm_kernel(
    const float* __restrict__ W_ih, const float* __restrict__ W_hh,
    const float* __restrict__ b_ih, const float* __restrict__ b_hh) {
  extern __shared__ char smem[];
  const int tid  = threadIdx.x;
  const int wz   = tid >> 5;
  const int lane = tid & 31;
  const int bg    = blockIdx.x >> 4;    // batch group
  const int slice = blockIdx.x & 15;    // h-col slice
  const int c0    = slice * 16;

  // ---- one-time: W slice (64 rows x 320 k) -> smem frags [plane][rw4][ks20][512B]
  // local row r: gate = r>>4, hcol = r&15 -> global row gate*256 + c0 + hcol
  for (int idx = tid; idx < 64 * 320; idx += NTHR) {
    int r = idx / 320, k = idx - r * 320;
    int gr = (r >> 4) * 256 + c0 + (r & 15);
    float v = (k < 256) ? W_hh[gr * 256 + k] : W_ih[gr * 64 + (k - 256)];
    __nv_bfloat16 hi = __float2bfloat16(v);
    __nv_bfloat16 lo = __float2bfloat16(v - __bfloat162float(hi));
    int rw = r >> 4, ks = k >> 4;
    int addr = rw * 10240 + ks * 512 + b_frag_off(r & 15, k & 15);
    *(__nv_bfloat16*)(smem + W_OFF + addr)       = hi;
    *(__nv_bfloat16*)(smem + W_OFF + WPL + addr) = lo;
  }

  // zero h region of hx (both planes, ks 0..15): 1024 x 16B chunks
  for (int i = tid; i < 1024; i += NTHR) {
    int off = (i >> 9) * 10240 + (i & 511) * 16;
    *(uint4*)(smem + HX_OFF + off) = make_uint4(0, 0, 0, 0);
  }

  // h copy-in chunk offsets: 4 x 16B per thread (16KB h region, both planes)
  int hoff[4];
#pragma unroll
  for (int i = 0; i < 4; i++) {
    int q = tid + i * NTHR;
    hoff[i] = (q >> 9) * 10240 + (q & 511) * 16;
  }
  // x stage: one 16B chunk per thread (4KB x region, both planes)
  const int xoff = (tid >> 7) * 10240 + 8192 + (tid & 127) * 16;
  // preload x(0)
  {
    const char* src = g_B + (size_t)bg * 20480;
    *(uint4*)(smem + HX_OFF + xoff) = __ldcg((const uint4*)(src + xoff));
  }

  // MMA mapping: rw = row-warp (16 rows = 1 gate's cols), kh = interleaved k-half
  const int rw = wz & 3;
  const int kh = wz >> 2;
  const char* pAh = smem + HX_OFF + kh * 512 + lane * 16;   // + j*1024
  const char* pAl = pAh + 10240;
  const char* pB  = smem + W_OFF + rw * 10240 + kh * 512 + lane * 16;

  // spill mapping
  const int sq  = lane >> 2;
  const int cp2 = (lane & 3) * 2;

  // epilogue mapping: one (b, hc) per thread
  const int eb = tid >> 4;
  const int ehc = tid & 15;
  float bias[4];
#pragma unroll
  for (int g = 0; g < 4; g++)
    bias[g] = b_ih[g * 256 + c0 + ehc] + b_hh[g * 256 + c0 + ehc];
  float cs = 0.f;
  const int puboff = slice * 512 + hx_frag_off(eb, ehc);

  unsigned int* flag = &g_cnt[bg * 32];
  __syncthreads();

  for (int t = 0; t < T_LEN; t++) {
    const char* ringT  = g_B + ((size_t)t * NBG + bg) * 20480;
    char*       ringT1 = g_B + ((size_t)(t + 1) * NBG + bg) * 20480;

    // ---- prefetch x(t+1) (pre-staged, h-independent) ----
    uint4 xv = __ldcg((const uint4*)(ringT1 + xoff));

    // ---- wait for h(t); issue h LDGs immediately after ----
    uint4 hv0, hv1, hv2, hv3;
    if (t) {
      unsigned int target = (unsigned int)(NSL * t);
      while (ld_acq(flag) < target) { }
      hv0 = __ldcg((const uint4*)(ringT + hoff[0]));
      hv1 = __ldcg((const uint4*)(ringT + hoff[1]));
      hv2 = __ldcg((const uint4*)(ringT + hoff[2]));
      hv3 = __ldcg((const uint4*)(ringT + hoff[3]));
    }

    float acc[8];
#pragma unroll
    for (int i = 0; i < 8; i++) acc[i] = 0.f;

    // ---- x-part MMAs (j = 8,9 -> ksteps 16..19) while h LDGs fly ----
#pragma unroll
    for (int j = 8; j < 10; j++) {
      uint4 aH = *(const uint4*)(pAh + j * 1024);
      uint4 aL = *(const uint4*)(pAl + j * 1024);
      uint4 bH = *(const uint4*)(pB + j * 1024);
      uint4 bL = *(const uint4*)(pB + WPL + j * 1024);
      mma16816(acc,     aH, bH.x, bH.y);
      mma16816(acc,     aH, bL.x, bL.y);
      mma16816(acc,     aL, bH.x, bH.y);
      mma16816(acc + 4, aH, bH.z, bH.w);
      mma16816(acc + 4, aH, bL.z, bL.w);
      mma16816(acc + 4, aL, bH.z, bH.w);
    }

    // ---- land h frags, barrier ----
    if (t) {
      *(uint4*)(smem + HX_OFF + hoff[0]) = hv0;
      *(uint4*)(smem + HX_OFF + hoff[1]) = hv1;
      *(uint4*)(smem + HX_OFF + hoff[2]) = hv2;
      *(uint4*)(smem + HX_OFF + hoff[3]) = hv3;
    }
    __syncthreads();

    // ---- h-part MMAs (j = 0..7 -> ksteps 0..15) ----
#pragma unroll
    for (int j = 0; j < 8; j++) {
      uint4 aH = *(const uint4*)(pAh + j * 1024);
      uint4 aL = *(const uint4*)(pAl + j * 1024);
      uint4 bH = *(const uint4*)(pB + j * 1024);
      uint4 bL = *(const uint4*)(pB + WPL + j * 1024);
      mma16816(acc,     aH, bH.x, bH.y);
      mma16816(acc,     aH, bL.x, bL.y);
      mma16816(acc,     aL, bH.x, bH.y);
      mma16816(acc + 4, aH, bH.z, bH.w);
      mma16816(acc + 4, aH, bL.z, bL.w);
      mma16816(acc + 4, aL, bH.z, bH.w);
    }

    // ---- spill partials: [kh][b16][70] ----
    {
      float* sp = (float*)(smem + SP_OFF) + kh * 16 * SPSTR;
      int r0 = rw * 16 + cp2;
#pragma unroll
      for (int tl = 0; tl < 2; tl++) {
        int r = r0 + tl * 8;
        *(float2*)(sp + sq * SPSTR + r) =
            make_float2(acc[tl * 4], acc[tl * 4 + 1]);
        *(float2*)(sp + (sq + 8) * SPSTR + r) =
            make_float2(acc[tl * 4 + 2], acc[tl * 4 + 3]);
      }
    }
    __syncthreads();

    // ---- epilogue: combine halves + bias, activations, publish h(t+1) ----
    {
      const float* s0 = (const float*)(smem + SP_OFF);
      const float* s1 = s0 + 16 * SPSTR;
      float gsum[4];
#pragma unroll
      for (int g = 0; g < 4; g++)
        gsum[g] = bias[g] + s0[eb * SPSTR + g * 16 + ehc] +
                  s1[eb * SPSTR + g * 16 + ehc];
      float iv = fsig(gsum[0]), fv = fsig(gsum[1]);
      float cv = ftanh(gsum[2]), ov = fsig(gsum[3]);
      float cn = fv * cs + iv * cv;
      cs = cn;
      float hvv = ov * ftanh(cn);
      __nv_bfloat16 hi = __float2bfloat16(hvv);
      __nv_bfloat16 lo = __float2bfloat16(hvv - __bfloat162float(hi));
      *(__nv_bfloat16*)(ringT1 + puboff)         = hi;
      *(__nv_bfloat16*)(ringT1 + 10240 + puboff) = lo;
      if (t == T_LEN - 1) g_Hf[bg * BB + eb][c0 + ehc] = hvv;
      *(uint4*)(smem + HX_OFF + xoff) = xv;   // stage x(t+1)
    }
    __syncthreads();
    if (tid == 0) red_rel(flag);
  }
}

// ---------------- fc ----------------
__global__ void fc_kernel(const float* __restrict__ fc_w,
                          const float* __restrict__ fc_b,
                          float* __restrict__ out) {
  int b = blockIdx.x;
  float s = g_Hf[b][threadIdx.x] * fc_w[threadIdx.x];
#pragma unroll
  for (int o = 16; o; o >>= 1) s += __shfl_xor_sync(0xFFFFFFFFu, s, o);
  __shared__ float ps[8];
  if ((threadIdx.x & 31) == 0) ps[threadIdx.x >> 5] = s;
  __syncthreads();
  if (threadIdx.x == 0) {
    float tt = 0.f;
#pragma unroll
    for (int i = 0; i < 8; i++) tt += ps[i];
    out[b] = tt + fc_b[0];
  }
}

// ---------------- launch ----------------
extern "C" void kernel_launch(void* const* d_in, const int* in_sizes, int n_in,
                              void* d_out, int out_size) {
  const float* x    = (const float*)d_in[0];
  const float* W_ih = (const float*)d_in[1];
  const float* W_hh = (const float*)d_in[2];
  const float* b_ih = (const float*)d_in[3];
  const float* b_hh = (const float*)d_in[4];
  const float* fc_w = (const float*)d_in[5];
  const float* fc_b = (const float*)d_in[6];
  float* out = (float*)d_out;

  static bool init = false;
  if (!init) {
    cudaFuncSetAttribute(lstm_kernel,
                         cudaFuncAttributeMaxDynamicSharedMemorySize, SMEM_TOTAL);
    init = true;
  }

  reset_kernel<<<1, 512>>>();
  xprep_kernel<<<65536, 256>>>(x);
  lstm_kernel<<<NBG * NSL, NTHR, SMEM_TOTAL>>>(W_ih, W_hh, b_ih, b_hh);
  fc_kernel<<<256, 256>>>(fc_w, fc_b, out);
}

// round 16
// speedup vs baseline: 1.5820x; 1.1633x over previous
#include <cuda_runtime.h>
#include <cuda_bf16.h>
#include <cstdint>

// ---------------- dims ----------------
#define T_LEN  1024
#define NBG    16       // batch groups (16 batch each)
#define NGG    8        // gate-slice CTAs per group
#define BB     16
#define NTHR   256

// ---------------- smem layout (bytes) ----------------
// W fragment regions: [hi_t01, hi_t23, lo_t01, lo_t23], each [gate4][ks20][lane32][16B]
#define WREG     40960
#define W_OFF    0
#define HX_OFF   (4 * WREG)            // 163840: hx hi [20][32][16B] then lo (+10240)
#define SP_OFF   (HX_OFF + 20480)      // 184320: 2 k-half spills, [b16][136 floats]
#define SP_HALF  8704
#define SMEM_TOTAL (SP_OFF + 2 * SP_HALF)   // 201728

// ---------------- static scratch ----------------
// hx ring in fragment layout: [t][bg]{hi 10240 | lo 10240}; x pre-staged at ks16..19
__device__ char          g_B[(size_t)(T_LEN + 1) * NBG * 20480];
__device__ float         g_Hf[256][256];
__device__ unsigned int  g_tag[NBG * 8 * 16];   // per-producer tags, 64B stride

// ---------------- helpers ----------------
__device__ __forceinline__ unsigned int ld_acq(const unsigned int* p) {
  unsigned int v;
  asm volatile("ld.acquire.gpu.global.u32 %0, [%1];" : "=r"(v) : "l"(p) : "memory");
  return v;
}
__device__ __forceinline__ void red_rel(unsigned int* p) {
  asm volatile("red.release.gpu.global.add.u32 [%0], 1;" :: "l"(p) : "memory");
}
__device__ __forceinline__ float fsig(float x) {
  x = fminf(fmaxf(x, -15.0f), 15.0f);
  return __fdividef(1.0f, 1.0f + __expf(-x));
}
__device__ __forceinline__ float ftanh(float x) {
  x = fminf(fmaxf(x, -15.0f), 15.0f);
  float e = __expf(-2.0f * x);
  return __fdividef(1.0f - e, 1.0f + e);
}
__device__ __forceinline__ void mma16816(float* d, const uint4& a,
                                         uint32_t b0, uint32_t b1) {
  asm volatile(
      "mma.sync.aligned.m16n8k16.row.col.f32.bf16.bf16.f32 "
      "{%0,%1,%2,%3}, {%4,%5,%6,%7}, {%8,%9}, {%0,%1,%2,%3};"
      : "+f"(d[0]), "+f"(d[1]), "+f"(d[2]), "+f"(d[3])
      : "r"(a.x), "r"(a.y), "r"(a.z), "r"(a.w), "r"(b0), "r"(b1));
}
// A-frag offset (batch b, k_in) within one kstep's 512B frag
__device__ __forceinline__ int hx_frag_off(int b, int k_in) {
  int u    = (k_in & 7) >> 1;
  int half = k_in & 1;
  int reg  = ((b >> 3) & 1) + ((k_in >> 3) & 1) * 2;
  return ((b & 7) * 4 + u) * 16 + reg * 4 + half * 2;
}

// ---------------- prep kernels ----------------
__global__ void reset_kernel() {
  if (threadIdx.x < NBG * 8 * 16) g_tag[threadIdx.x] = 0u;
}
// stage x (hi/lo) into ring k-steps 16..19 for all t
__global__ void xprep_kernel(const float* __restrict__ x) {
  int id  = blockIdx.x * 256 + threadIdx.x;      // 16,777,216
  int i   = id & 63;
  int t   = (id >> 6) & 1023;
  int bgl = id >> 16;
  float v = x[(size_t)bgl * (T_LEN * 64) + t * 64 + i];
  __nv_bfloat16 hi = __float2bfloat16(v);
  __nv_bfloat16 lo = __float2bfloat16(v - __bfloat162float(hi));
  int bg = bgl >> 4, b = bgl & 15;
  int ks = 16 + (i >> 4);
  int off = ks * 512 + hx_frag_off(b, i & 15);
  char* base = g_B + ((size_t)t * NBG + bg) * 20480;
  *(__nv_bfloat16*)(base + off)         = hi;
  *(__nv_bfloat16*)(base + 10240 + off) = lo;
}

// ---------------- main persistent kernel ----------------
__global__ void __launch_bounds__(NTHR, 1) lstm_kernel(
    const float* __restrict__ W_ih, const float* __restrict__ W_hh,
    const float* __restrict__ b_ih, const float* __restrict__ b_hh) {
  extern __shared__ char smem[];
  const int tid  = threadIdx.x;
  const int w    = tid >> 5;
  const int lane = tid & 31;
  const int bg   = blockIdx.x >> 3;
  const int gg   = blockIdx.x & 7;
  const int c0   = gg * 32;

  // ---- one-time: W slice -> smem fragment-major (hi/lo, tiles split) ----
  for (int idx = tid; idx < 128 * 320; idx += NTHR) {
    int r = idx / 320, k = idx - r * 320;
    int gate = r >> 5;
    int gr = gate * 256 + c0 + (r & 31);
    float v = (k < 256) ? W_hh[gr * 256 + k] : W_ih[gr * 64 + (k - 256)];
    __nv_bfloat16 hi = __float2bfloat16(v);
    __nv_bfloat16 lo = __float2bfloat16(v - __bfloat162float(hi));
    int ks = k >> 4, ki = k & 15;
    int u = (ki & 7) >> 1, half = ki & 1, rh = (ki >> 3) & 1;
    int j = (r >> 3) & 3;
    int off = gate * 10240 + ks * 512 + ((r & 7) * 4 + u) * 16 +
              (j & 1) * 8 + rh * 4 + half * 2;
    int regidx = j >> 1;
    *(__nv_bfloat16*)(smem + W_OFF + regidx * WREG + off)       = hi;
    *(__nv_bfloat16*)(smem + W_OFF + (2 + regidx) * WREG + off) = lo;
  }

  // zero h region of hx (both planes, ks 0..15)
  for (int i = tid; i < 1024; i += NTHR) {
    int off = (i >> 9) * 10240 + (i & 511) * 16;
    *(uint4*)(smem + HX_OFF + off) = make_uint4(0, 0, 0, 0);
  }
  // x stage: one 16B chunk per thread (4KB x region, both planes); preload x(0)
  const int xoff = (tid >> 7) * 10240 + 8192 + (tid & 127) * 16;
  {
    const char* src = g_B + (size_t)bg * 20480;
    *(uint4*)(smem + HX_OFF + xoff) = __ldcg((const uint4*)(src + xoff));
  }

  // ---- MMA mapping: ns = gate slice, kh = CONTIGUOUS k-half ----
  const int ns = w & 3;
  const int kh = w >> 2;
  const char* pAh = smem + HX_OFF + lane * 16;   // + ks*512 (+10240 for lo)
  const char* pBb = smem + W_OFF + ns * 10240 + lane * 16;

  // per-half h copy-in: 4 x 16B chunks per thread over half's 8KB (8 ks x 2 planes)
  int hoffH[4];
#pragma unroll
  for (int i = 0; i < 4; i++) {
    int m = (tid & 127) + i * 128;                 // 0..511
    hoffH[i] = (m >> 8) * 10240 + (kh * 8 + ((m >> 5) & 7)) * 512 + (m & 31) * 16;
  }
  // tags: this half waits on producers kh*4 + (lane&3); own tag = gg
  const unsigned int* wtag = g_tag + bg * 128 + (kh * 4 + (lane & 3)) * 16;
  unsigned int*       mytag = g_tag + bg * 128 + gg * 16;

  // ---- epilogue mapping (R6 verbatim) ----
  const int ehc = tid & 31;
  const int eb  = tid >> 5;
  float bias[4];
#pragma unroll
  for (int g = 0; g < 4; g++)
    bias[g] = b_ih[g * 256 + c0 + ehc] + b_hh[g * 256 + c0 + ehc];
  float cs[2] = {0.f, 0.f};
  const int eks  = gg * 2 + (ehc >> 4);
  const int ekin = ehc & 15;

  __syncthreads();

  for (int t = 0; t < T_LEN; t++) {
    const char* ringT  = g_B + ((size_t)t * NBG + bg) * 20480;
    char*       ringT1 = g_B + ((size_t)(t + 1) * NBG + bg) * 20480;

    // ---- prefetch x(t+1) (pre-staged, h-independent) ----
    uint4 xv = __ldcg((const uint4*)(ringT1 + xoff));

    // ---- per-half wait on own 4 producers; then issue h LDGs ----
    uint4 hv0, hv1, hv2, hv3;
    if (t) {
      unsigned int target = (unsigned int)t;
      while (true) {
        unsigned int v = ld_acq(wtag);
        if (__all_sync(0xFFFFFFFFu, v >= target)) break;
      }
      hv0 = __ldcg((const uint4*)(ringT + hoffH[0]));
      hv1 = __ldcg((const uint4*)(ringT + hoffH[1]));
      hv2 = __ldcg((const uint4*)(ringT + hoffH[2]));
      hv3 = __ldcg((const uint4*)(ringT + hoffH[3]));
    }

    float acc[16];
#pragma unroll
    for (int i = 0; i < 16; i++) acc[i] = 0.f;

    // ---- x-part MMAs (this half's 2 x-ksteps) while h LDGs fly ----
#pragma unroll
    for (int jx = 0; jx < 2; jx++) {
      int ks = 16 + kh * 2 + jx;
      uint4 aH  = *(const uint4*)(pAh + ks * 512);
      uint4 aL  = *(const uint4*)(pAh + 10240 + ks * 512);
      uint4 bh0 = *(const uint4*)(pBb + ks * 512);
      uint4 bh1 = *(const uint4*)(pBb + WREG + ks * 512);
      uint4 bl0 = *(const uint4*)(pBb + 2 * WREG + ks * 512);
      uint4 bl1 = *(const uint4*)(pBb + 3 * WREG + ks * 512);
      mma16816(acc + 0,  aH, bh0.x, bh0.y);
      mma16816(acc + 0,  aH, bl0.x, bl0.y);
      mma16816(acc + 0,  aL, bh0.x, bh0.y);
      mma16816(acc + 4,  aH, bh0.z, bh0.w);
      mma16816(acc + 4,  aH, bl0.z, bl0.w);
      mma16816(acc + 4,  aL, bh0.z, bh0.w);
      mma16816(acc + 8,  aH, bh1.x, bh1.y);
      mma16816(acc + 8,  aH, bl1.x, bl1.y);
      mma16816(acc + 8,  aL, bh1.x, bh1.y);
      mma16816(acc + 12, aH, bh1.z, bh1.w);
      mma16816(acc + 12, aH, bl1.z, bl1.w);
      mma16816(acc + 12, aL, bh1.z, bh1.w);
    }

    // ---- land this half's h frags; half-barrier ----
    if (t) {
      *(uint4*)(smem + HX_OFF + hoffH[0]) = hv0;
      *(uint4*)(smem + HX_OFF + hoffH[1]) = hv1;
      *(uint4*)(smem + HX_OFF + hoffH[2]) = hv2;
      *(uint4*)(smem + HX_OFF + hoffH[3]) = hv3;
      asm volatile("bar.sync %0, 128;" :: "r"(1 + kh) : "memory");
    }

    // ---- h-part MMAs (contiguous: ks = kh*8 + j) ----
#pragma unroll
    for (int j = 0; j < 8; j++) {
      int ks = kh * 8 + j;
      uint4 aH  = *(const uint4*)(pAh + ks * 512);
      uint4 aL  = *(const uint4*)(pAh + 10240 + ks * 512);
      uint4 bh0 = *(const uint4*)(pBb + ks * 512);
      uint4 bh1 = *(const uint4*)(pBb + WREG + ks * 512);
      uint4 bl0 = *(const uint4*)(pBb + 2 * WREG + ks * 512);
      uint4 bl1 = *(const uint4*)(pBb + 3 * WREG + ks * 512);
      mma16816(acc + 0,  aH, bh0.x, bh0.y);
      mma16816(acc + 0,  aH, bl0.x, bl0.y);
      mma16816(acc + 0,  aL, bh0.x, bh0.y);
      mma16816(acc + 4,  aH, bh0.z, bh0.w);
      mma16816(acc + 4,  aH, bl0.z, bl0.w);
      mma16816(acc + 4,  aL, bh0.z, bh0.w);
      mma16816(acc + 8,  aH, bh1.x, bh1.y);
      mma16816(acc + 8,  aH, bl1.x, bl1.y);
      mma16816(acc + 8,  aL, bh1.x, bh1.y);
      mma16816(acc + 12, aH, bh1.z, bh1.w);
      mma16816(acc + 12, aH, bl1.z, bl1.w);
      mma16816(acc + 12, aL, bh1.z, bh1.w);
    }

    // ---- spill partials: [kh][b16][136] ----
    {
      float* sp = (float*)(smem + SP_OFF) + kh * 2176;
      int q = lane >> 2, cp2 = (lane & 3) * 2;
#pragma unroll
      for (int tl = 0; tl < 4; tl++) {
        int r = ns * 32 + tl * 8 + cp2;
        *(float2*)(sp + q * 136 + r)       = make_float2(acc[tl * 4], acc[tl * 4 + 1]);
        *(float2*)(sp + (q + 8) * 136 + r) = make_float2(acc[tl * 4 + 2], acc[tl * 4 + 3]);
      }
    }
    __syncthreads();

    // ---- epilogue: combine halves, activations, publish h(t+1), stage x(t+1) ----
    {
      const float* s0 = (const float*)(smem + SP_OFF);
      const float* s1 = s0 + 2176;
#pragma unroll
      for (int uu = 0; uu < 2; uu++) {
        int b = eb + uu * 8;
        float gi = s0[b * 136 +  0 + ehc] + s1[b * 136 +  0 + ehc] + bias[0];
        float gf = s0[b * 136 + 32 + ehc] + s1[b * 136 + 32 + ehc] + bias[1];
        float gc = s0[b * 136 + 64 + ehc] + s1[b * 136 + 64 + ehc] + bias[2];
        float go = s0[b * 136 + 96 + ehc] + s1[b * 136 + 96 + ehc] + bias[3];
        float iv = fsig(gi), fv = fsig(gf), cv = ftanh(gc), ov = fsig(go);
        float cn = fv * cs[uu] + iv * cv;
        cs[uu] = cn;
        float hvv = ov * ftanh(cn);
        __nv_bfloat16 hi = __float2bfloat16(hvv);
        __nv_bfloat16 lo = __float2bfloat16(hvv - __bfloat162float(hi));
        int off = eks * 512 + hx_frag_off(b, ekin);
        *(__nv_bfloat16*)(ringT1 + off)         = hi;
        *(__nv_bfloat16*)(ringT1 + 10240 + off) = lo;
        if (t == T_LEN - 1) g_Hf[bg * BB + b][c0 + ehc] = hvv;
      }
      // stage x(t+1) (x(t) fully consumed above)
      *(uint4*)(smem + HX_OFF + xoff) = xv;
    }
    __syncthreads();
    if (tid == 0) red_rel(mytag);
  }
}

// ---------------- fc ----------------
__global__ void fc_kernel(const float* __restrict__ fc_w,
                          const float* __restrict__ fc_b,
                          float* __restrict__ out) {
  int b = blockIdx.x;
  float s = g_Hf[b][threadIdx.x] * fc_w[threadIdx.x];
#pragma unroll
  for (int o = 16; o; o >>= 1) s += __shfl_xor_sync(0xFFFFFFFFu, s, o);
  __shared__ float ps[8];
  if ((threadIdx.x & 31) == 0) ps[threadIdx.x >> 5] = s;
  __syncthreads();
  if (threadIdx.x == 0) {
    float tt = 0.f;
#pragma unroll
    for (int i = 0; i < 8; i++) tt += ps[i];
    out[b] = tt + fc_b[0];
  }
}

// ---------------- launch ----------------
extern "C" void kernel_launch(void* const* d_in, const int* in_sizes, int n_in,
                              void* d_out, int out_size) {
  const float* x    = (const float*)d_in[0];
  const float* W_ih = (const float*)d_in[1];
  const float* W_hh = (const float*)d_in[2];
  const float* b_ih = (const float*)d_in[3];
  const float* b_hh = (const float*)d_in[4];
  const float* fc_w = (const float*)d_in[5];
  const float* fc_b = (const float*)d_in[6];
  float* out = (float*)d_out;

  static bool init = false;
  if (!init) {
    cudaFuncSetAttribute(lstm_kernel,
                         cudaFuncAttributeMaxDynamicSharedMemorySize, SMEM_TOTAL);
    init = true;
  }

  reset_kernel<<<2, 1024>>>();
  xprep_kernel<<<65536, 256>>>(x);
  lstm_kernel<<<NBG * NGG, NTHR, SMEM_TOTAL>>>(W_ih, W_hh, b_ih, b_hh);
  fc_kernel<<<256, 256>>>(fc_w, fc_b, out);
}